// round 14
// baseline (speedup 1.0000x reference)
#include <cuda_runtime.h>
#include <cuda_fp16.h>

#define H     4096
#define K     32
#define WO    4065
#define HP2   2048            // half2 (uint) pitch of scratch rows
#define COUT  65              // outputs per pass-2 chunk (1 + 2*32)

// fp16 scratch: 4096 rows x 2048 half2 = 33.5 MB — intended L2-resident
__device__ unsigned g_tmp[(size_t)H * HP2];

__device__ __forceinline__ int sk(int x) { return x + (x >> 4); }
__device__ __forceinline__ int hs(int i) { return i + (i >> 3); }

__device__ __forceinline__ float4 ldcs4(const float4* p) {
    float4 r;
    asm volatile("ld.global.cs.v4.f32 {%0,%1,%2,%3}, [%4];"
                 : "=f"(r.x), "=f"(r.y), "=f"(r.z), "=f"(r.w) : "l"(p));
    return r;
}
// write-through: no L2 line allocation -> scratch stays resident
__device__ __forceinline__ void stwt(float* p, float v) {
    asm volatile("st.global.wt.f32 [%0], %1;" :: "l"(p), "f"(v));
}

// ---------------------------------------------------------------------------
// Pass 1 (unchanged, near-roofline): dist + horizontal 32-wide box sum -> fp16
// ---------------------------------------------------------------------------
__global__ void __launch_bounds__(256, 8)
row_pass(const float* __restrict__ img,
         const float* __restrict__ som,
         const float* __restrict__ var)
{
    __shared__ float d[4352];
    __shared__ float irow[32];

    const int y = blockIdx.x;
    const int t = threadIdx.x;

    if (t < 32) irow[t] = img[((y & 31) << 5) + t];
    __syncthreads();

    const float4* s4 = (const float4*)(som + (size_t)y * H);
    const float4* v4 = (const float4*)(var + (size_t)y * H);
    const float4  iv = ((const float4*)irow)[t & 7];

#pragma unroll
    for (int k = 0; k < 4; k++) {
        int i4 = t + (k << 8);
        float4 s = ldcs4(s4 + i4);
        float4 v = ldcs4(v4 + i4);
        int x = i4 << 2;
        float f0 = iv.x - s.x, f1 = iv.y - s.y, f2 = iv.z - s.z, f3 = iv.w - s.w;
        d[sk(x)]     = __fdividef(f0 * f0, v.x + 1e-8f);
        d[sk(x + 1)] = __fdividef(f1 * f1, v.y + 1e-8f);
        d[sk(x + 2)] = __fdividef(f2 * f2, v.z + 1e-8f);
        d[sk(x + 3)] = __fdividef(f3 * f3, v.w + 1e-8f);
    }
    __syncthreads();

    const int base = t << 4;
    const int jmax = (base < WO) ? min(16, WO - base) : 0;
    float res[16];
#pragma unroll
    for (int j = 0; j < 16; j++) res[j] = 0.f;

    if (jmax > 0) {
        float s = 0.f;
#pragma unroll
        for (int i = 0; i < K; i++) s += d[sk(base + i)];
        res[0] = s;
#pragma unroll
        for (int j = 1; j < 16; j++) {
            s += d[sk(base + j + K - 1)] - d[sk(base + j - 1)];
            if (j < jmax) res[j] = s;
        }
    }
    __syncthreads();

    unsigned* hbuf = (unsigned*)d;
#pragma unroll
    for (int p = 0; p < 8; p++) {
        __half2 h = __floats2half2_rn(res[2 * p], res[2 * p + 1]);
        hbuf[hs((t << 3) + p)] = *(unsigned*)&h;
    }
    __syncthreads();

    unsigned* grow = g_tmp + (size_t)y * HP2;
#pragma unroll
    for (int k = 0; k < 8; k++) {
        int idx = t + (k << 8);
        if (idx < 2033) grow[idx] = hbuf[hs(idx)];   // default policy: stays in L2
    }
}

// ---------------------------------------------------------------------------
// Pass 2 (R13 structure): one column per thread, 32-deep fp32 register ring,
// ONE merged LDG per row pair of lanes, full-efficiency row stores — now with
// write-through output stores so the scratch is never evicted from L2.
// ---------------------------------------------------------------------------
__global__ void __launch_bounds__(256)
col_pass(float* __restrict__ out)
{
    const int x   = blockIdx.x * 256 + threadIdx.x;      // output column
    const int par = (x & 1) ? 16 : 0;
    const unsigned* col = g_tmp + (x >> 1);
    const bool ok = x < WO;

    const int j0 = blockIdx.y * COUT;

    unsigned u[32];
    float    pv[32];
    float    s = 0.f;

#pragma unroll
    for (int i = 0; i < 32; i++)
        u[i] = col[(size_t)(j0 + i) * HP2];
#pragma unroll
    for (int i = 0; i < 32; i++) {
        float v = __half2float(__ushort_as_half((unsigned short)(u[i] >> par)));
        pv[i] = v;
        s += v;
    }
    if (ok) stwt(out + (size_t)j0 * WO + x, s);

#pragma unroll
    for (int blk = 0; blk < 2; blk++) {
        const int rbase = j0 + 32 + blk * 32;
        const int jb    = j0 + 1 + blk * 32;
#pragma unroll
        for (int i = 0; i < 32; i++) {
            int r = min(rbase + i, H - 1);
            u[i] = col[(size_t)r * HP2];
        }
#pragma unroll
        for (int i = 0; i < 32; i++) {
            float v = __half2float(__ushort_as_half((unsigned short)(u[i] >> par)));
            s += v - pv[i];
            pv[i] = v;
            int j = jb + i;
            if (ok && j < WO) stwt(out + (size_t)j * WO + x, s);
        }
    }
}

// ---------------------------------------------------------------------------
extern "C" void kernel_launch(void* const* d_in, const int* in_sizes, int n_in,
                              void* d_out, int out_size)
{
    const float* img = (const float*)d_in[0];   // [32,32]
    const float* som = (const float*)d_in[1];   // [4096,4096]
    const float* var = (const float*)d_in[2];   // [4096,4096]
    float*       out = (float*)d_out;           // [4065,4065]

    row_pass<<<H, 256>>>(img, som, var);

    dim3 grid2(16,                              // 4096 cols / 256
               (WO + COUT - 1) / COUT);         // 63 -> 1008 CTAs
    col_pass<<<grid2, 256>>>(out);
}